// round 1
// baseline (speedup 1.0000x reference)
#include <cuda_runtime.h>
#include <cuda_bf16.h>

// Problem constants
#define BB 1024
#define TT 512
#define EMB 100
#define H1 128
#define H2 64
#define G1 512        // 4*H1 gate width
#define G2 256        // 4*H2
#define K1 228        // EMB + H1 combined contraction dim (layer1)
#define K2 192        // H1 + H2 (layer2)
#define NG1 57        // K1/4 float4 k-groups
#define NG2 48        // K2/4
#define SG1 24        // k-groups of W1 cached in shared (rest streamed from L2)
#define ROWS 8        // batch rows per CTA
#define NBLK 128      // 1024/8

typedef unsigned long long ull;

// ---------------- scratch (static device memory: allocation-free) ----------------
__device__ float g_W1P[NG1 * G1 * 4];    // [g][j][u], k = 4g+u; k<100 -> W1_ih, else W1_hh
__device__ float g_W2P[NG2 * G2 * 4];
__device__ float g_b1[G1];
__device__ float g_b2[G2];
__device__ float g_hs1[BB * TT * H1];    // layer-1 hidden states, 268 MB
__device__ float g_hn[BB * H2];          // layer-2 final hidden

// ---------------- helpers ----------------
__device__ __forceinline__ ull pack2(float lo, float hi) {
    ull r; asm("mov.b64 %0, {%1,%2};" : "=l"(r) : "f"(lo), "f"(hi)); return r;
}
__device__ __forceinline__ void unpack2(ull v, float& lo, float& hi) {
    asm("mov.b64 {%0,%1}, %2;" : "=f"(lo), "=f"(hi) : "l"(v));
}
__device__ __forceinline__ ull fma2(ull a, ull b, ull c) {
    ull d; asm("fma.rn.f32x2 %0, %1, %2, %3;" : "=l"(d) : "l"(a), "l"(b), "l"(c)); return d;
}
__device__ __forceinline__ float sigf(float x) {
    return __fdividef(1.f, 1.f + __expf(-x));
}
__device__ __forceinline__ float tanh_(float x) {
    // 2*sigmoid(2x)-1 ; __expf rel-err ~2^-21, saturates correctly at +-inf
    return __fdividef(2.f, 1.f + __expf(-2.f * x)) - 1.f;
}

// one k-slice: acc over 8 rows (4 x f32x2) with scalar weight w
__device__ __forceinline__ void gstep8(const ulonglong2* __restrict__ uhx, int k, float w,
                                       ull& a01, ull& a23, ull& a45, ull& a67) {
    ull w2 = pack2(w, w);
    ulonglong2 p0 = uhx[k * 2];
    ulonglong2 p1 = uhx[k * 2 + 1];
    a01 = fma2(p0.x, w2, a01);
    a23 = fma2(p0.y, w2, a23);
    a45 = fma2(p1.x, w2, a45);
    a67 = fma2(p1.y, w2, a67);
}

// ---------------- prep: build packed k-major weights ----------------
__global__ void prep_kernel(const float* __restrict__ W1ih, const float* __restrict__ W1hh,
                            const float* __restrict__ b1ih, const float* __restrict__ b1hh,
                            const float* __restrict__ W2ih, const float* __restrict__ W2hh,
                            const float* __restrict__ b2ih, const float* __restrict__ b2hh) {
    int idx = blockIdx.x * blockDim.x + threadIdx.x;
    if (idx < NG1 * G1 * 4) {
        int u = idx & 3;
        int j = (idx >> 2) & (G1 - 1);
        int g = idx >> 11;              // (G1*4)=2048=2^11
        int k = 4 * g + u;
        g_W1P[idx] = (k < EMB) ? W1ih[j * EMB + k] : W1hh[j * H1 + (k - EMB)];
    }
    if (idx < NG2 * G2 * 4) {
        int u = idx & 3;
        int j = (idx >> 2) & (G2 - 1);
        int g = idx >> 10;              // (G2*4)=1024=2^10
        int k = 4 * g + u;
        g_W2P[idx] = (k < H1) ? W2ih[j * H1 + k] : W2hh[j * H2 + (k - H1)];
    }
    if (idx < G1) g_b1[idx] = b1ih[idx] + b1hh[idx];
    if (idx < G2) g_b2[idx] = b2ih[idx] + b2hh[idx];
}

// ---------------- layer 1: fused input-proj + recurrence ----------------
// smem: sW[SG1*2048] | hx[228*8] | gsh[8*512] | sb[512]  = 222336 bytes
#define SMEM1_FLOATS (SG1 * G1 * 4 + K1 * ROWS + ROWS * G1 + G1)

__global__ void __launch_bounds__(512, 1) lstm1_kernel(const float* __restrict__ X) {
    extern __shared__ float sm[];
    float* sW  = sm;
    float* hx  = sW + SG1 * G1 * 4;       // [k][r] transposed operand buffer, k=0..227
    float* gsh = hx + K1 * ROWS;          // [r][512] raw gates
    float* sb  = gsh + ROWS * G1;

    const int tid  = threadIdx.x;          // gate column j = tid
    const int row0 = blockIdx.x * ROWS;

    const float4* W1P4 = (const float4*)g_W1P;
    float4* sW4 = (float4*)sW;
    for (int i = tid; i < SG1 * G1; i += 512) sW4[i] = W1P4[i];
    sb[tid] = g_b1[tid];
    for (int i = tid; i < H1 * ROWS; i += 512) hx[EMB * ROWS + i] = 0.f;  // h := 0

    const int an = tid & 127;              // activation lane: hidden index
    const int ar = tid >> 7;               // activation row (0..3), also handles ar+4
    float c0 = 0.f, c1 = 0.f;
    const ulonglong2* uhx = (const ulonglong2*)hx;
    __syncthreads();

    for (int t = 0; t < TT; ++t) {
        // stage x_t transposed: hx[k*8 + r] = X[row0+r][t][k]   (800 elems)
        {
            int idx = tid;
            int r = idx / EMB, k = idx - r * EMB;
            hx[k * ROWS + r] = X[((row0 + r) * TT + t) * EMB + k];
            idx = tid + 512;
            if (idx < ROWS * EMB) {
                int r2 = idx / EMB, k2 = idx - r2 * EMB;
                hx[k2 * ROWS + r2] = X[((row0 + r2) * TT + t) * EMB + k2];
            }
        }
        __syncthreads();

        float b = sb[tid];
        ull a01 = pack2(b, b), a23 = a01, a45 = a01, a67 = a01;

        #pragma unroll 4
        for (int gi = 0; gi < SG1; ++gi) {
            float4 w4 = sW4[gi * G1 + tid];
            gstep8(uhx, 4 * gi + 0, w4.x, a01, a23, a45, a67);
            gstep8(uhx, 4 * gi + 1, w4.y, a01, a23, a45, a67);
            gstep8(uhx, 4 * gi + 2, w4.z, a01, a23, a45, a67);
            gstep8(uhx, 4 * gi + 3, w4.w, a01, a23, a45, a67);
        }
        #pragma unroll 4
        for (int gi = SG1; gi < NG1; ++gi) {
            float4 w4 = W1P4[gi * G1 + tid];    // L2-resident stream
            gstep8(uhx, 4 * gi + 0, w4.x, a01, a23, a45, a67);
            gstep8(uhx, 4 * gi + 1, w4.y, a01, a23, a45, a67);
            gstep8(uhx, 4 * gi + 2, w4.z, a01, a23, a45, a67);
            gstep8(uhx, 4 * gi + 3, w4.w, a01, a23, a45, a67);
        }

        float v0, v1;
        unpack2(a01, v0, v1); gsh[0 * G1 + tid] = v0; gsh[1 * G1 + tid] = v1;
        unpack2(a23, v0, v1); gsh[2 * G1 + tid] = v0; gsh[3 * G1 + tid] = v1;
        unpack2(a45, v0, v1); gsh[4 * G1 + tid] = v0; gsh[5 * G1 + tid] = v1;
        unpack2(a67, v0, v1); gsh[6 * G1 + tid] = v0; gsh[7 * G1 + tid] = v1;
        __syncthreads();

        // activation: thread handles (ar, an) and (ar+4, an)
        {
            const float* gr = gsh + ar * G1;
            float ii = gr[an], ff = gr[H1 + an], gg = gr[2 * H1 + an], oo = gr[3 * H1 + an];
            c0 = sigf(ff) * c0 + sigf(ii) * tanh_(gg);
            float h0 = sigf(oo) * tanh_(c0);

            const float* gr2 = gsh + (ar + 4) * G1;
            float i2 = gr2[an], f2 = gr2[H1 + an], g2 = gr2[2 * H1 + an], o2 = gr2[3 * H1 + an];
            c1 = sigf(f2) * c1 + sigf(i2) * tanh_(g2);
            float h1 = sigf(o2) * tanh_(c1);

            hx[(EMB + an) * ROWS + ar]     = h0;
            hx[(EMB + an) * ROWS + ar + 4] = h1;
            g_hs1[((row0 + ar)     * TT + t) * H1 + an] = h0;
            g_hs1[((row0 + ar + 4) * TT + t) * H1 + an] = h1;
        }
        // next iteration's post-stage __syncthreads orders h writes vs gate reads
    }
}

// ---------------- layer 2: fused input-proj + recurrence (W fully in smem) ----------------
#define SMEM2_FLOATS (NG2 * G2 * 4 + K2 * ROWS + ROWS * G2 + G2)

__global__ void __launch_bounds__(512, 1) lstm2_kernel() {
    extern __shared__ float sm[];
    float* sW  = sm;
    float* hx  = sW + NG2 * G2 * 4;       // [k][r], k=0..191 (128 input + 64 h)
    float* gsh = hx + K2 * ROWS;          // [r][256]
    float* sb  = gsh + ROWS * G2;

    const int tid  = threadIdx.x;
    const int row0 = blockIdx.x * ROWS;

    const float4* W2P4 = (const float4*)g_W2P;
    float4* sW4 = (float4*)sW;
    for (int i = tid; i < NG2 * G2; i += 512) sW4[i] = W2P4[i];
    if (tid < G2) sb[tid] = g_b2[tid];
    for (int i = tid; i < H2 * ROWS; i += 512) hx[H1 * ROWS + i] = 0.f;

    const int j  = tid & 255;             // gate column
    const int q  = tid >> 8;              // row half: rows 4q..4q+3
    const int an = tid & 63;              // activation hidden idx
    const int arr = tid >> 6;             // activation row 0..7
    float c = 0.f, hlast = 0.f;
    const ulonglong2* uhx = (const ulonglong2*)hx;
    __syncthreads();

    for (int t = 0; t < TT; ++t) {
        for (int idx = tid; idx < ROWS * H1; idx += 512) {
            int r = idx >> 7, k = idx & 127;
            hx[k * ROWS + r] = g_hs1[((row0 + r) * TT + t) * H1 + k];
        }
        __syncthreads();

        float b = sb[j];
        ull aA = pack2(b, b), aB = aA;     // rows (4q,4q+1) and (4q+2,4q+3)

        #pragma unroll 4
        for (int gi = 0; gi < NG2; ++gi) {
            float4 w4 = sW4[gi * G2 + j];
            {
                ull w2 = pack2(w4.x, w4.x);
                ulonglong2 p = uhx[(4 * gi + 0) * 2 + q];
                aA = fma2(p.x, w2, aA); aB = fma2(p.y, w2, aB);
            }
            {
                ull w2 = pack2(w4.y, w4.y);
                ulonglong2 p = uhx[(4 * gi + 1) * 2 + q];
                aA = fma2(p.x, w2, aA); aB = fma2(p.y, w2, aB);
            }
            {
                ull w2 = pack2(w4.z, w4.z);
                ulonglong2 p = uhx[(4 * gi + 2) * 2 + q];
                aA = fma2(p.x, w2, aA); aB = fma2(p.y, w2, aB);
            }
            {
                ull w2 = pack2(w4.w, w4.w);
                ulonglong2 p = uhx[(4 * gi + 3) * 2 + q];
                aA = fma2(p.x, w2, aA); aB = fma2(p.y, w2, aB);
            }
        }

        float v0, v1;
        unpack2(aA, v0, v1); gsh[(4 * q + 0) * G2 + j] = v0; gsh[(4 * q + 1) * G2 + j] = v1;
        unpack2(aB, v0, v1); gsh[(4 * q + 2) * G2 + j] = v0; gsh[(4 * q + 3) * G2 + j] = v1;
        __syncthreads();

        {
            const float* gr = gsh + arr * G2;
            float ii = gr[an], ff = gr[H2 + an], gg = gr[2 * H2 + an], oo = gr[3 * H2 + an];
            c = sigf(ff) * c + sigf(ii) * tanh_(gg);
            hlast = sigf(oo) * tanh_(c);
            hx[(H1 + an) * ROWS + arr] = hlast;
        }
    }
    g_hn[(row0 + arr) * H2 + an] = hlast;
}

// ---------------- head: FC(64->32) relu, FC(32->1), sigmoid ----------------
__global__ void head_kernel(const float* __restrict__ fc1w, const float* __restrict__ fc1b,
                            const float* __restrict__ fc2w, const float* __restrict__ fc2b,
                            float* __restrict__ out) {
    __shared__ float sw1[32 * 64];
    __shared__ float sb1[32];
    __shared__ float sw2[32];
    int tid = threadIdx.x;  // 256
    for (int i = tid; i < 32 * 64; i += 256) sw1[i] = fc1w[i];
    if (tid < 32) { sb1[tid] = fc1b[tid]; sw2[tid] = fc2w[tid]; }
    __syncthreads();

    int b = blockIdx.x * 256 + tid;
    const float* h = g_hn + b * H2;
    float z = fc2b[0];
    #pragma unroll
    for (int i = 0; i < 32; ++i) {
        float s = sb1[i];
        const float* w = sw1 + i * 64;
        #pragma unroll
        for (int k = 0; k < 64; ++k) s += h[k] * w[k];
        z += fmaxf(s, 0.f) * sw2[i];
    }
    out[b] = __fdividef(1.f, 1.f + __expf(-z));
}

// ---------------- launch ----------------
extern "C" void kernel_launch(void* const* d_in, const int* in_sizes, int n_in,
                              void* d_out, int out_size) {
    const float* X    = (const float*)d_in[0];
    const float* W1ih = (const float*)d_in[1];
    const float* W1hh = (const float*)d_in[2];
    const float* b1ih = (const float*)d_in[3];
    const float* b1hh = (const float*)d_in[4];
    const float* W2ih = (const float*)d_in[5];
    const float* W2hh = (const float*)d_in[6];
    const float* b2ih = (const float*)d_in[7];
    const float* b2hh = (const float*)d_in[8];
    const float* fc1w = (const float*)d_in[9];
    const float* fc1b = (const float*)d_in[10];
    const float* fc2w = (const float*)d_in[11];
    const float* fc2b = (const float*)d_in[12];
    float* out = (float*)d_out;

    const int smem1 = SMEM1_FLOATS * (int)sizeof(float);  // 222336
    const int smem2 = SMEM2_FLOATS * (int)sizeof(float);  // 211968
    cudaFuncSetAttribute(lstm1_kernel, cudaFuncAttributeMaxDynamicSharedMemorySize, smem1);
    cudaFuncSetAttribute(lstm2_kernel, cudaFuncAttributeMaxDynamicSharedMemorySize, smem2);

    prep_kernel<<<456, 256>>>(W1ih, W1hh, b1ih, b1hh, W2ih, W2hh, b2ih, b2hh);
    lstm1_kernel<<<NBLK, 512, smem1>>>(X);
    lstm2_kernel<<<NBLK, 512, smem2>>>();
    head_kernel<<<4, 256>>>(fc1w, fc1b, fc2w, fc2b, out);
}

// round 4
// speedup vs baseline: 1.2702x; 1.2702x over previous
#include <cuda_runtime.h>
#include <cuda_bf16.h>

// Problem constants
#define BB 1024
#define TT 512
#define EMB 100
#define H1 128
#define H2 64
#define G1 512        // 4*H1 gate width
#define G2 256        // 4*H2
#define K1 228        // EMB + H1 combined contraction dim (layer1)
#define K2 192        // H1 + H2 (layer2)
#define NG1 57        // K1/4 float4 k-groups
#define NG2 48        // K2/4
#define SG1 25        // k-groups of W1 cached in shared (32 streamed from L2)
#define ROWS 8        // batch rows per CTA
#define NBLK 128      // 1024/8

typedef unsigned long long ull;

// ---------------- scratch (static device memory: allocation-free) ----------------
__device__ float g_W1P[NG1 * G1 * 4];    // [g][j][u], k = 4g+u; k<100 -> W1_ih, else W1_hh
__device__ float g_W2P[NG2 * G2 * 4];
__device__ float g_b1[G1];
__device__ float g_b2[G2];
// layer-1 hidden states, TRANSPOSED per CTA-block: [block][t][k*8+r]
__device__ float g_hs1[BB * TT * H1];
// layer-2 final hidden, transposed: [block][k*8+r]
__device__ float g_hn[BB * H2];

// ---------------- helpers ----------------
__device__ __forceinline__ ull pack2(float lo, float hi) {
    ull r; asm("mov.b64 %0, {%1,%2};" : "=l"(r) : "f"(lo), "f"(hi)); return r;
}
__device__ __forceinline__ void unpack2(ull v, float& lo, float& hi) {
    asm("mov.b64 {%0,%1}, %2;" : "=f"(lo), "=f"(hi) : "l"(v));
}
__device__ __forceinline__ ull fma2(ull a, ull b, ull c) {
    ull d; asm("fma.rn.f32x2 %0, %1, %2, %3;" : "=l"(d) : "l"(a), "l"(b), "l"(c)); return d;
}
__device__ __forceinline__ float sigf(float x) {
    return __fdividef(1.f, 1.f + __expf(-x));
}
__device__ __forceinline__ float tanh_(float x) {
    return __fdividef(2.f, 1.f + __expf(-2.f * x)) - 1.f;
}

// one k-slice: 8 rows x 2 cols, 2 broadcast LDS.128 feed 8 FFMA2
__device__ __forceinline__ void kslice(const ulonglong2* __restrict__ uhx, int k,
                                       float wa, float wb,
                                       ull& A01, ull& A23, ull& A45, ull& A67,
                                       ull& B01, ull& B23, ull& B45, ull& B67) {
    ulonglong2 p0 = uhx[2 * k];
    ulonglong2 p1 = uhx[2 * k + 1];
    ull wa2 = pack2(wa, wa);
    ull wb2 = pack2(wb, wb);
    A01 = fma2(p0.x, wa2, A01); A23 = fma2(p0.y, wa2, A23);
    A45 = fma2(p1.x, wa2, A45); A67 = fma2(p1.y, wa2, A67);
    B01 = fma2(p0.x, wb2, B01); B23 = fma2(p0.y, wb2, B23);
    B45 = fma2(p1.x, wb2, B45); B67 = fma2(p1.y, wb2, B67);
}

#define KS(kk, wa, wb) kslice(uhx, (kk), (wa), (wb), A01, A23, A45, A67, B01, B23, B45, B67)

// ---------------- prep: build packed k-major weights ----------------
__global__ void prep_kernel(const float* __restrict__ W1ih, const float* __restrict__ W1hh,
                            const float* __restrict__ b1ih, const float* __restrict__ b1hh,
                            const float* __restrict__ W2ih, const float* __restrict__ W2hh,
                            const float* __restrict__ b2ih, const float* __restrict__ b2hh) {
    int idx = blockIdx.x * blockDim.x + threadIdx.x;
    if (idx < NG1 * G1 * 4) {
        int u = idx & 3;
        int j = (idx >> 2) & (G1 - 1);
        int g = idx >> 11;
        int k = 4 * g + u;
        g_W1P[idx] = (k < EMB) ? W1ih[j * EMB + k] : W1hh[j * H1 + (k - EMB)];
    }
    if (idx < NG2 * G2 * 4) {
        int u = idx & 3;
        int j = (idx >> 2) & (G2 - 1);
        int g = idx >> 10;
        int k = 4 * g + u;
        g_W2P[idx] = (k < H1) ? W2ih[j * H1 + k] : W2hh[j * H2 + (k - H1)];
    }
    if (idx < G1) g_b1[idx] = b1ih[idx] + b1hh[idx];
    if (idx < G2) g_b2[idx] = b2ih[idx] + b2hh[idx];
}

// ---------------- layer 1: fused input-proj + recurrence ----------------
// smem: sW[25*2048] | hx[228*8] | gsh[8*512]  = 228480 bytes
#define SMEM1_FLOATS (SG1 * G1 * 4 + K1 * ROWS + ROWS * G1)

__global__ void __launch_bounds__(256, 1) lstm1_kernel(const float* __restrict__ X) {
    extern __shared__ float sm[];
    float* sW  = sm;
    float* hx  = sW + SG1 * G1 * 4;       // [k][r], k=0..227
    float* gsh = hx + K1 * ROWS;          // [r][512]

    const int tid  = threadIdx.x;
    const int bid  = blockIdx.x;
    const int row0 = bid * ROWS;
    const int j0 = tid, j1 = tid + 256;

    const float4* W1P4 = (const float4*)g_W1P;
    float4* sW4 = (float4*)sW;
    for (int i = tid; i < SG1 * G1; i += 256) sW4[i] = W1P4[i];
    for (int i = tid; i < H1 * ROWS; i += 256) hx[EMB * ROWS + i] = 0.f;  // h := 0

    const float ba = g_b1[j0];
    const float bb = g_b1[j1];

    const int an = tid & 127;             // activation hidden index
    const int p  = tid >> 7;              // 0..1, rows p, p+2, p+4, p+6
    float c[4] = {0.f, 0.f, 0.f, 0.f};

    const ulonglong2* uhx = (const ulonglong2*)hx;
    float4* hx4 = (float4*)hx;
    float* gout = g_hs1 + (size_t)bid * TT * (H1 * ROWS);  // [t][1024]
    const float4* Ws = W1P4 + SG1 * G1;   // streamed groups [32][512]
    __syncthreads();

    for (int t = 0; t < TT; ++t) {
        // stage x_t transposed: hx[k*8 + r]
        const float* Xt = X + ((size_t)row0 * TT + t) * EMB;
        for (int idx = tid; idx < ROWS * EMB; idx += 256) {
            int r = idx / EMB, k = idx - r * EMB;
            hx[k * ROWS + r] = Xt[(size_t)r * TT * EMB + k];
        }
        __syncthreads();

        // coalesced write-out of h(t-1) (1 LDS.128 + 1 STG.128)
        if (t > 0) {
            float4 hv = hx4[(EMB * ROWS) / 4 + tid];
            ((float4*)(gout + (size_t)(t - 1) * 1024))[tid] = hv;
        }

        ull A01 = pack2(ba, ba), A23 = A01, A45 = A01, A67 = A01;
        ull B01 = pack2(bb, bb), B23 = B01, B45 = B01, B67 = B01;

        // preload streamed chunk 0 early (hidden under smem-group compute)
        float4 bufA[8], bufB[8];
        #pragma unroll
        for (int u = 0; u < 4; ++u) {
            bufA[u]     = Ws[u * G1 + j0];
            bufA[4 + u] = Ws[u * G1 + j1];
        }

        // smem-cached groups
        #pragma unroll 5
        for (int gi = 0; gi < SG1; ++gi) {
            float4 wa = sW4[gi * G1 + j0];
            float4 wb = sW4[gi * G1 + j1];
            KS(4 * gi + 0, wa.x, wb.x);
            KS(4 * gi + 1, wa.y, wb.y);
            KS(4 * gi + 2, wa.z, wb.z);
            KS(4 * gi + 3, wa.w, wb.w);
        }

        // streamed groups: 8 chunks of 4, double-buffered
        #pragma unroll 1
        for (int ch = 0; ch < 8; ch += 2) {
            #pragma unroll
            for (int u = 0; u < 4; ++u) {          // load chunk ch+1
                bufB[u]     = Ws[((ch + 1) * 4 + u) * G1 + j0];
                bufB[4 + u] = Ws[((ch + 1) * 4 + u) * G1 + j1];
            }
            #pragma unroll
            for (int u = 0; u < 4; ++u) {          // compute chunk ch
                int gi = SG1 + ch * 4 + u;
                KS(4 * gi + 0, bufA[u].x, bufA[4 + u].x);
                KS(4 * gi + 1, bufA[u].y, bufA[4 + u].y);
                KS(4 * gi + 2, bufA[u].z, bufA[4 + u].z);
                KS(4 * gi + 3, bufA[u].w, bufA[4 + u].w);
            }
            if (ch + 2 < 8) {
                #pragma unroll
                for (int u = 0; u < 4; ++u) {      // load chunk ch+2
                    bufA[u]     = Ws[((ch + 2) * 4 + u) * G1 + j0];
                    bufA[4 + u] = Ws[((ch + 2) * 4 + u) * G1 + j1];
                }
            }
            #pragma unroll
            for (int u = 0; u < 4; ++u) {          // compute chunk ch+1
                int gi = SG1 + (ch + 1) * 4 + u;
                KS(4 * gi + 0, bufB[u].x, bufB[4 + u].x);
                KS(4 * gi + 1, bufB[u].y, bufB[4 + u].y);
                KS(4 * gi + 2, bufB[u].z, bufB[4 + u].z);
                KS(4 * gi + 3, bufB[u].w, bufB[4 + u].w);
            }
        }

        float v0, v1;
        unpack2(A01, v0, v1); gsh[0 * G1 + j0] = v0; gsh[1 * G1 + j0] = v1;
        unpack2(A23, v0, v1); gsh[2 * G1 + j0] = v0; gsh[3 * G1 + j0] = v1;
        unpack2(A45, v0, v1); gsh[4 * G1 + j0] = v0; gsh[5 * G1 + j0] = v1;
        unpack2(A67, v0, v1); gsh[6 * G1 + j0] = v0; gsh[7 * G1 + j0] = v1;
        unpack2(B01, v0, v1); gsh[0 * G1 + j1] = v0; gsh[1 * G1 + j1] = v1;
        unpack2(B23, v0, v1); gsh[2 * G1 + j1] = v0; gsh[3 * G1 + j1] = v1;
        unpack2(B45, v0, v1); gsh[4 * G1 + j1] = v0; gsh[5 * G1 + j1] = v1;
        unpack2(B67, v0, v1); gsh[6 * G1 + j1] = v0; gsh[7 * G1 + j1] = v1;
        __syncthreads();

        // activation: 4 (row, an) pairs per thread
        #pragma unroll
        for (int q = 0; q < 4; ++q) {
            int r = p + 2 * q;
            const float* gr = gsh + r * G1;
            float ii = gr[an], ff = gr[H1 + an], gg = gr[2 * H1 + an], oo = gr[3 * H1 + an];
            c[q] = sigf(ff) * c[q] + sigf(ii) * tanh_(gg);
            hx[(EMB + an) * ROWS + r] = sigf(oo) * tanh_(c[q]);
        }
    }
    __syncthreads();
    ((float4*)(gout + (size_t)(TT - 1) * 1024))[tid] = hx4[(EMB * ROWS) / 4 + tid];
}

// ---------------- layer 2: W fully in smem, 128 threads x 2 cols ----------------
#define SMEM2_FLOATS (NG2 * G2 * 4 + K2 * ROWS + ROWS * G2)

__global__ void __launch_bounds__(128, 1) lstm2_kernel() {
    extern __shared__ float sm[];
    float* sW  = sm;                      // 48*1024 floats
    float* hx  = sW + NG2 * G2 * 4;       // [k][r], k=0..191
    float* gsh = hx + K2 * ROWS;          // [r][256]

    const int tid = threadIdx.x;
    const int bid = blockIdx.x;
    const int j0 = tid, j1 = tid + 128;

    const float4* W2P4 = (const float4*)g_W2P;
    float4* sW4 = (float4*)sW;
    for (int i = tid; i < NG2 * G2; i += 128) sW4[i] = W2P4[i];
    for (int i = tid; i < H2 * ROWS; i += 128) hx[H1 * ROWS + i] = 0.f;

    const float ba = g_b2[j0];
    const float bb = g_b2[j1];

    const int an = tid & 63;
    const int p  = tid >> 6;              // 0..1, rows p, p+2, p+4, p+6
    float c[4] = {0.f, 0.f, 0.f, 0.f};

    const ulonglong2* uhx = (const ulonglong2*)hx;
    float4* hx4 = (float4*)hx;
    const float4* src = (const float4*)(g_hs1 + (size_t)bid * TT * 1024);
    __syncthreads();

    for (int t = 0; t < TT; ++t) {
        // stage hs1(t): already [k][r]; straight copy, 2x (LDG.128 + STS.128)
        float4 s0 = src[(size_t)t * 256 + tid];
        float4 s1 = src[(size_t)t * 256 + tid + 128];
        hx4[tid] = s0;
        hx4[tid + 128] = s1;
        __syncthreads();

        ull A01 = pack2(ba, ba), A23 = A01, A45 = A01, A67 = A01;
        ull B01 = pack2(bb, bb), B23 = B01, B45 = B01, B67 = B01;

        #pragma unroll 6
        for (int gi = 0; gi < NG2; ++gi) {
            float4 wa = sW4[gi * G2 + j0];
            float4 wb = sW4[gi * G2 + j1];
            KS(4 * gi + 0, wa.x, wb.x);
            KS(4 * gi + 1, wa.y, wb.y);
            KS(4 * gi + 2, wa.z, wb.z);
            KS(4 * gi + 3, wa.w, wb.w);
        }

        float v0, v1;
        unpack2(A01, v0, v1); gsh[0 * G2 + j0] = v0; gsh[1 * G2 + j0] = v1;
        unpack2(A23, v0, v1); gsh[2 * G2 + j0] = v0; gsh[3 * G2 + j0] = v1;
        unpack2(A45, v0, v1); gsh[4 * G2 + j0] = v0; gsh[5 * G2 + j0] = v1;
        unpack2(A67, v0, v1); gsh[6 * G2 + j0] = v0; gsh[7 * G2 + j0] = v1;
        unpack2(B01, v0, v1); gsh[0 * G2 + j1] = v0; gsh[1 * G2 + j1] = v1;
        unpack2(B23, v0, v1); gsh[2 * G2 + j1] = v0; gsh[3 * G2 + j1] = v1;
        unpack2(B45, v0, v1); gsh[4 * G2 + j1] = v0; gsh[5 * G2 + j1] = v1;
        unpack2(B67, v0, v1); gsh[6 * G2 + j1] = v0; gsh[7 * G2 + j1] = v1;
        __syncthreads();

        #pragma unroll
        for (int q = 0; q < 4; ++q) {
            int r = p + 2 * q;
            const float* gr = gsh + r * G2;
            float ii = gr[an], ff = gr[H2 + an], gg = gr[2 * H2 + an], oo = gr[3 * H2 + an];
            c[q] = sigf(ff) * c[q] + sigf(ii) * tanh_(gg);
            hx[(H1 + an) * ROWS + r] = sigf(oo) * tanh_(c[q]);
        }
    }
    __syncthreads();
    ((float4*)g_hn)[bid * 128 + tid] = hx4[(H1 * ROWS) / 4 + tid];
}

// ---------------- head: FC(64->32) relu, FC(32->1), sigmoid ----------------
__global__ void head_kernel(const float* __restrict__ fc1w, const float* __restrict__ fc1b,
                            const float* __restrict__ fc2w, const float* __restrict__ fc2b,
                            float* __restrict__ out) {
    __shared__ float sw1[32 * 64];
    __shared__ float sb1[32];
    __shared__ float sw2[32];
    int tid = threadIdx.x;  // 256
    for (int i = tid; i < 32 * 64; i += 256) sw1[i] = fc1w[i];
    if (tid < 32) { sb1[tid] = fc1b[tid]; sw2[tid] = fc2w[tid]; }
    __syncthreads();

    int b = blockIdx.x * 256 + tid;
    // g_hn transposed: [block][k*8+r]
    const float* h = g_hn + (size_t)(b >> 3) * (H2 * ROWS) + (b & 7);
    float hr[64];
    #pragma unroll
    for (int k = 0; k < 64; ++k) hr[k] = h[k * ROWS];
    float z = fc2b[0];
    #pragma unroll
    for (int i = 0; i < 32; ++i) {
        float s = sb1[i];
        const float* w = sw1 + i * 64;
        #pragma unroll
        for (int k = 0; k < 64; ++k) s += hr[k] * w[k];
        z += fmaxf(s, 0.f) * sw2[i];
    }
    out[b] = __fdividef(1.f, 1.f + __expf(-z));
}

// ---------------- launch ----------------
extern "C" void kernel_launch(void* const* d_in, const int* in_sizes, int n_in,
                              void* d_out, int out_size) {
    const float* X    = (const float*)d_in[0];
    const float* W1ih = (const float*)d_in[1];
    const float* W1hh = (const float*)d_in[2];
    const float* b1ih = (const float*)d_in[3];
    const float* b1hh = (const float*)d_in[4];
    const float* W2ih = (const float*)d_in[5];
    const float* W2hh = (const float*)d_in[6];
    const float* b2ih = (const float*)d_in[7];
    const float* b2hh = (const float*)d_in[8];
    const float* fc1w = (const float*)d_in[9];
    const float* fc1b = (const float*)d_in[10];
    const float* fc2w = (const float*)d_in[11];
    const float* fc2b = (const float*)d_in[12];
    float* out = (float*)d_out;

    const int smem1 = SMEM1_FLOATS * (int)sizeof(float);  // 228480
    const int smem2 = SMEM2_FLOATS * (int)sizeof(float);  // 210944
    cudaFuncSetAttribute(lstm1_kernel, cudaFuncAttributeMaxDynamicSharedMemorySize, smem1);
    cudaFuncSetAttribute(lstm2_kernel, cudaFuncAttributeMaxDynamicSharedMemorySize, smem2);

    prep_kernel<<<456, 256>>>(W1ih, W1hh, b1ih, b1hh, W2ih, W2hh, b2ih, b2hh);
    lstm1_kernel<<<NBLK, 256, smem1>>>(X);
    lstm2_kernel<<<NBLK, 128, smem2>>>();
    head_kernel<<<4, 256>>>(fc1w, fc1b, fc2w, fc2b, out);
}

// round 5
// speedup vs baseline: 1.3660x; 1.0754x over previous
#include <cuda_runtime.h>
#include <cuda_bf16.h>

// Problem constants
#define BB 1024
#define TT 512
#define EMB 100
#define H1 128
#define H2 64
#define G1 512        // 4*H1 gate width
#define G2 256        // 4*H2
#define K1 228        // EMB + H1 combined contraction dim (layer1)
#define K2 192        // H1 + H2 (layer2)
#define NG1 57        // K1/4 float4 k-groups
#define NG2 48        // K2/4
#define SG1 23        // k-groups of W1 cached in shared
#define H0_STREAM 6   // streamed groups computed by half0 (groups 23..28)
#define H1_STREAM 28  // streamed groups computed by half1 (groups 29..56)
#define ROWS 8        // batch rows per CTA
#define NBLK 128      // 1024/8

typedef unsigned long long ull;

// ---------------- scratch (static device memory: allocation-free) ----------------
__device__ float g_W1P[NG1 * G1 * 4];    // [g][j][u], k = 4g+u; k<100 -> W1_ih, else W1_hh
__device__ float g_W2P[NG2 * G2 * 4];
__device__ float g_b1[G1];
__device__ float g_b2[G2];
// layer-1 hidden states, TRANSPOSED per CTA-block: [block][t][k*8+r]
__device__ float g_hs1[BB * TT * H1];
// layer-2 final hidden, transposed: [block][k*8+r]
__device__ float g_hn[BB * H2];

// ---------------- helpers ----------------
__device__ __forceinline__ ull pack2(float lo, float hi) {
    ull r; asm("mov.b64 %0, {%1,%2};" : "=l"(r) : "f"(lo), "f"(hi)); return r;
}
__device__ __forceinline__ void unpack2(ull v, float& lo, float& hi) {
    asm("mov.b64 {%0,%1}, %2;" : "=f"(lo), "=f"(hi) : "l"(v));
}
__device__ __forceinline__ ull fma2(ull a, ull b, ull c) {
    ull d; asm("fma.rn.f32x2 %0, %1, %2, %3;" : "=l"(d) : "l"(a), "l"(b), "l"(c)); return d;
}
__device__ __forceinline__ float sigf(float x) {
    return __fdividef(1.f, 1.f + __expf(-x));
}
__device__ __forceinline__ float tanh_(float x) {
    return __fdividef(2.f, 1.f + __expf(-2.f * x)) - 1.f;
}

// one k-slice: 8 rows x 2 cols, 2 broadcast LDS.128 feed 8 FFMA2
__device__ __forceinline__ void kslice(const ulonglong2* __restrict__ uhx, int k,
                                       float wa, float wb,
                                       ull& A01, ull& A23, ull& A45, ull& A67,
                                       ull& B01, ull& B23, ull& B45, ull& B67) {
    ulonglong2 p0 = uhx[2 * k];
    ulonglong2 p1 = uhx[2 * k + 1];
    ull wa2 = pack2(wa, wa);
    ull wb2 = pack2(wb, wb);
    A01 = fma2(p0.x, wa2, A01); A23 = fma2(p0.y, wa2, A23);
    A45 = fma2(p1.x, wa2, A45); A67 = fma2(p1.y, wa2, A67);
    B01 = fma2(p0.x, wb2, B01); B23 = fma2(p0.y, wb2, B23);
    B45 = fma2(p1.x, wb2, B45); B67 = fma2(p1.y, wb2, B67);
}
#define KS(kk, wa, wb) kslice(uhx, (kk), (wa), (wb), A01, A23, A45, A67, B01, B23, B45, B67)
#define KSG(gg, w4a, w4b) do { \
    KS(4*(gg)+0, (w4a).x, (w4b).x); \
    KS(4*(gg)+1, (w4a).y, (w4b).y); \
    KS(4*(gg)+2, (w4a).z, (w4b).z); \
    KS(4*(gg)+3, (w4a).w, (w4b).w); } while (0)

// one k-slice, 8 rows x 1 col (lstm2)
__device__ __forceinline__ void kslice1(const ulonglong2* __restrict__ uhx, int k, float w,
                                        ull& A01, ull& A23, ull& A45, ull& A67) {
    ulonglong2 p0 = uhx[2 * k];
    ulonglong2 p1 = uhx[2 * k + 1];
    ull w2 = pack2(w, w);
    A01 = fma2(p0.x, w2, A01); A23 = fma2(p0.y, w2, A23);
    A45 = fma2(p1.x, w2, A45); A67 = fma2(p1.y, w2, A67);
}

// ---------------- prep: build packed k-major weights ----------------
__global__ void prep_kernel(const float* __restrict__ W1ih, const float* __restrict__ W1hh,
                            const float* __restrict__ b1ih, const float* __restrict__ b1hh,
                            const float* __restrict__ W2ih, const float* __restrict__ W2hh,
                            const float* __restrict__ b2ih, const float* __restrict__ b2hh) {
    int idx = blockIdx.x * blockDim.x + threadIdx.x;
    if (idx < NG1 * G1 * 4) {
        int u = idx & 3;
        int j = (idx >> 2) & (G1 - 1);
        int g = idx >> 11;
        int k = 4 * g + u;
        g_W1P[idx] = (k < EMB) ? W1ih[j * EMB + k] : W1hh[j * H1 + (k - EMB)];
    }
    if (idx < NG2 * G2 * 4) {
        int u = idx & 3;
        int j = (idx >> 2) & (G2 - 1);
        int g = idx >> 10;
        int k = 4 * g + u;
        g_W2P[idx] = (k < H1) ? W2ih[j * H1 + k] : W2hh[j * H2 + (k - H1)];
    }
    if (idx < G1) g_b1[idx] = b1ih[idx] + b1hh[idx];
    if (idx < G2) g_b2[idx] = b2ih[idx] + b2hh[idx];
}

// ---------------- layer 1: fused input-proj + recurrence, k-split across 512 threads ----------------
// smem: sW[23*2048] | hx[228*8] | gshA[8*512] | gshB[8*512]  = 228480 bytes
#define SMEM1_FLOATS (SG1 * G1 * 4 + K1 * ROWS + 2 * ROWS * G1)

__global__ void __launch_bounds__(512, 1) lstm1_kernel(const float* __restrict__ X) {
    extern __shared__ float sm[];
    float* sW   = sm;
    float* hx   = sW + SG1 * G1 * 4;       // [k][r], k=0..227
    float* gshA = hx + K1 * ROWS;          // [r][512] partial gates (resident half + bias)
    float* gshB = gshA + ROWS * G1;        // [r][512] partial gates (streamed half)

    const int tid  = threadIdx.x;
    const int bid  = blockIdx.x;
    const int row0 = bid * ROWS;
    const int j0 = tid & 255, j1 = j0 + 256;
    const bool half0 = (tid < 256);

    const float4* W1P4 = (const float4*)g_W1P;
    float4* sW4 = (float4*)sW;
    for (int i = tid; i < SG1 * G1; i += 512) sW4[i] = W1P4[i];
    for (int i = tid; i < H1 * ROWS; i += 512) hx[EMB * ROWS + i] = 0.f;  // h := 0

    const float ba = half0 ? g_b1[j0] : 0.f;
    const float bb = half0 ? g_b1[j1] : 0.f;

    const int an = tid & 127;              // activation hidden index
    const int ar = tid >> 7;               // 0..3, rows ar and ar+4
    float c0 = 0.f, c1 = 0.f;

    const ulonglong2* uhx = (const ulonglong2*)hx;
    float4* hx4 = (float4*)hx;
    float* gout = g_hs1 + (size_t)bid * TT * (H1 * ROWS);  // [t][1024]
    float* gsh  = half0 ? gshA : gshB;
    __syncthreads();

    for (int t = 0; t < TT; ++t) {
        // stage x_t transposed: hx[k*8 + r]
        const float* Xt = X + ((size_t)row0 * TT + t) * EMB;
        {
            int idx = tid;
            if (idx < ROWS * EMB) {
                int r = idx / EMB, k = idx - r * EMB;
                hx[k * ROWS + r] = Xt[(size_t)r * TT * EMB + k];
            }
            idx = tid + 512;
            if (idx < ROWS * EMB) {
                int r = idx / EMB, k = idx - r * EMB;
                hx[k * ROWS + r] = Xt[(size_t)r * TT * EMB + k];
            }
        }
        __syncthreads();

        // coalesced write-out of h(t-1)
        if (t > 0 && tid < 256) {
            ((float4*)(gout + (size_t)(t - 1) * 1024))[tid] = hx4[(EMB * ROWS) / 4 + tid];
        }

        ull A01 = pack2(ba, ba), A23 = A01, A45 = A01, A67 = A01;
        ull B01 = pack2(bb, bb), B23 = B01, B45 = B01, B67 = B01;

        if (half0) {
            // resident groups 0..22 + streamed groups 23..28 (3 chunks of 2)
            const float4* Ws = W1P4;
            float4 bufA[4], bufB[4];
            bufA[0] = Ws[23 * G1 + j0]; bufA[1] = Ws[23 * G1 + j1];
            bufA[2] = Ws[24 * G1 + j0]; bufA[3] = Ws[24 * G1 + j1];

            #pragma unroll 5
            for (int gi = 0; gi < SG1; ++gi) {
                float4 wa = sW4[gi * G1 + j0];
                float4 wb = sW4[gi * G1 + j1];
                KSG(gi, wa, wb);
            }

            bufB[0] = Ws[25 * G1 + j0]; bufB[1] = Ws[25 * G1 + j1];
            bufB[2] = Ws[26 * G1 + j0]; bufB[3] = Ws[26 * G1 + j1];
            KSG(23, bufA[0], bufA[1]);
            KSG(24, bufA[2], bufA[3]);
            bufA[0] = Ws[27 * G1 + j0]; bufA[1] = Ws[27 * G1 + j1];
            bufA[2] = Ws[28 * G1 + j0]; bufA[3] = Ws[28 * G1 + j1];
            KSG(25, bufB[0], bufB[1]);
            KSG(26, bufB[2], bufB[3]);
            KSG(27, bufA[0], bufA[1]);
            KSG(28, bufA[2], bufA[3]);
        } else {
            // streamed groups 29..56: 14 chunks of 2, double-buffered
            const float4* Ws = W1P4 + 29 * G1;
            float4 bufA[4], bufB[4];
            bufA[0] = Ws[0 * G1 + j0]; bufA[1] = Ws[0 * G1 + j1];
            bufA[2] = Ws[1 * G1 + j0]; bufA[3] = Ws[1 * G1 + j1];

            #pragma unroll 1
            for (int ch = 0; ch < 14; ch += 2) {
                int g0 = 2 * ch;             // local group of bufA
                bufB[0] = Ws[(g0 + 2) * G1 + j0]; bufB[1] = Ws[(g0 + 2) * G1 + j1];
                bufB[2] = Ws[(g0 + 3) * G1 + j0]; bufB[3] = Ws[(g0 + 3) * G1 + j1];
                KSG(29 + g0 + 0, bufA[0], bufA[1]);
                KSG(29 + g0 + 1, bufA[2], bufA[3]);
                if (ch + 2 < 14) {
                    bufA[0] = Ws[(g0 + 4) * G1 + j0]; bufA[1] = Ws[(g0 + 4) * G1 + j1];
                    bufA[2] = Ws[(g0 + 5) * G1 + j0]; bufA[3] = Ws[(g0 + 5) * G1 + j1];
                }
                KSG(29 + g0 + 2, bufB[0], bufB[1]);
                KSG(29 + g0 + 3, bufB[2], bufB[3]);
            }
        }

        float v0, v1;
        unpack2(A01, v0, v1); gsh[0 * G1 + j0] = v0; gsh[1 * G1 + j0] = v1;
        unpack2(A23, v0, v1); gsh[2 * G1 + j0] = v0; gsh[3 * G1 + j0] = v1;
        unpack2(A45, v0, v1); gsh[4 * G1 + j0] = v0; gsh[5 * G1 + j0] = v1;
        unpack2(A67, v0, v1); gsh[6 * G1 + j0] = v0; gsh[7 * G1 + j0] = v1;
        unpack2(B01, v0, v1); gsh[0 * G1 + j1] = v0; gsh[1 * G1 + j1] = v1;
        unpack2(B23, v0, v1); gsh[2 * G1 + j1] = v0; gsh[3 * G1 + j1] = v1;
        unpack2(B45, v0, v1); gsh[4 * G1 + j1] = v0; gsh[5 * G1 + j1] = v1;
        unpack2(B67, v0, v1); gsh[6 * G1 + j1] = v0; gsh[7 * G1 + j1] = v1;
        __syncthreads();

        // activation: rows ar and ar+4 for hidden an; gates = gshA + gshB
        {
            const float* ga = gshA + ar * G1;
            const float* gb = gshB + ar * G1;
            float ii = ga[an] + gb[an];
            float ff = ga[H1 + an] + gb[H1 + an];
            float gg = ga[2 * H1 + an] + gb[2 * H1 + an];
            float oo = ga[3 * H1 + an] + gb[3 * H1 + an];
            c0 = sigf(ff) * c0 + sigf(ii) * tanh_(gg);
            hx[(EMB + an) * ROWS + ar] = sigf(oo) * tanh_(c0);

            const float* ga2 = gshA + (ar + 4) * G1;
            const float* gb2 = gshB + (ar + 4) * G1;
            float i2 = ga2[an] + gb2[an];
            float f2 = ga2[H1 + an] + gb2[H1 + an];
            float g2 = ga2[2 * H1 + an] + gb2[2 * H1 + an];
            float o2 = ga2[3 * H1 + an] + gb2[3 * H1 + an];
            c1 = sigf(f2) * c1 + sigf(i2) * tanh_(g2);
            hx[(EMB + an) * ROWS + ar + 4] = sigf(o2) * tanh_(c1);
        }
    }
    __syncthreads();
    if (tid < 256)
        ((float4*)(gout + (size_t)(TT - 1) * 1024))[tid] = hx4[(EMB * ROWS) / 4 + tid];
}

// ---------------- layer 2: W fully in smem, 256 threads x 1 col x 8 rows ----------------
#define SMEM2_FLOATS (NG2 * G2 * 4 + K2 * ROWS + ROWS * G2)

__global__ void __launch_bounds__(256, 1) lstm2_kernel() {
    extern __shared__ float sm[];
    float* sW  = sm;                      // 48*1024 floats
    float* hx  = sW + NG2 * G2 * 4;       // [k][r], k=0..191
    float* gsh = hx + K2 * ROWS;          // [r][256]

    const int tid = threadIdx.x;
    const int bid = blockIdx.x;
    const int j = tid;                    // gate column

    const float4* W2P4 = (const float4*)g_W2P;
    float4* sW4 = (float4*)sW;
    for (int i = tid; i < NG2 * G2; i += 256) sW4[i] = W2P4[i];
    for (int i = tid; i < H2 * ROWS; i += 256) hx[H1 * ROWS + i] = 0.f;

    const float bj = g_b2[j];

    const int an = tid & 63;
    const int ar = tid >> 6;              // 0..3, rows ar and ar+4
    float c0 = 0.f, c1 = 0.f;

    const ulonglong2* uhx = (const ulonglong2*)hx;
    float4* hx4 = (float4*)hx;
    const float4* src = (const float4*)(g_hs1 + (size_t)bid * TT * 1024);
    __syncthreads();

    for (int t = 0; t < TT; ++t) {
        // stage hs1(t): already [k][r]; straight copy
        hx4[tid] = src[(size_t)t * 256 + tid];
        __syncthreads();

        ull A01 = pack2(bj, bj), A23 = A01, A45 = A01, A67 = A01;

        #pragma unroll 8
        for (int gi = 0; gi < NG2; ++gi) {
            float4 w = sW4[gi * G2 + j];
            kslice1(uhx, 4 * gi + 0, w.x, A01, A23, A45, A67);
            kslice1(uhx, 4 * gi + 1, w.y, A01, A23, A45, A67);
            kslice1(uhx, 4 * gi + 2, w.z, A01, A23, A45, A67);
            kslice1(uhx, 4 * gi + 3, w.w, A01, A23, A45, A67);
        }

        float v0, v1;
        unpack2(A01, v0, v1); gsh[0 * G2 + j] = v0; gsh[1 * G2 + j] = v1;
        unpack2(A23, v0, v1); gsh[2 * G2 + j] = v0; gsh[3 * G2 + j] = v1;
        unpack2(A45, v0, v1); gsh[4 * G2 + j] = v0; gsh[5 * G2 + j] = v1;
        unpack2(A67, v0, v1); gsh[6 * G2 + j] = v0; gsh[7 * G2 + j] = v1;
        __syncthreads();

        {
            const float* gr = gsh + ar * G2;
            float ii = gr[an], ff = gr[H2 + an], gg = gr[2 * H2 + an], oo = gr[3 * H2 + an];
            c0 = sigf(ff) * c0 + sigf(ii) * tanh_(gg);
            hx[(H1 + an) * ROWS + ar] = sigf(oo) * tanh_(c0);

            const float* gr2 = gsh + (ar + 4) * G2;
            float i2 = gr2[an], f2 = gr2[H2 + an], g2 = gr2[2 * H2 + an], o2 = gr2[3 * H2 + an];
            c1 = sigf(f2) * c1 + sigf(i2) * tanh_(g2);
            hx[(H1 + an) * ROWS + ar + 4] = sigf(o2) * tanh_(c1);
        }
    }
    __syncthreads();
    if (tid < 128)
        ((float4*)g_hn)[bid * 128 + tid] = hx4[(H1 * ROWS) / 4 + tid];
}

// ---------------- head: FC(64->32) relu, FC(32->1), sigmoid ----------------
__global__ void head_kernel(const float* __restrict__ fc1w, const float* __restrict__ fc1b,
                            const float* __restrict__ fc2w, const float* __restrict__ fc2b,
                            float* __restrict__ out) {
    __shared__ float sw1[32 * 64];
    __shared__ float sb1[32];
    __shared__ float sw2[32];
    int tid = threadIdx.x;  // 256
    for (int i = tid; i < 32 * 64; i += 256) sw1[i] = fc1w[i];
    if (tid < 32) { sb1[tid] = fc1b[tid]; sw2[tid] = fc2w[tid]; }
    __syncthreads();

    int b = blockIdx.x * 256 + tid;
    // g_hn transposed: [block][k*8+r]
    const float* h = g_hn + (size_t)(b >> 3) * (H2 * ROWS) + (b & 7);
    float hr[64];
    #pragma unroll
    for (int k = 0; k < 64; ++k) hr[k] = h[k * ROWS];
    float z = fc2b[0];
    #pragma unroll
    for (int i = 0; i < 32; ++i) {
        float s = sb1[i];
        const float* w = sw1 + i * 64;
        #pragma unroll
        for (int k = 0; k < 64; ++k) s += hr[k] * w[k];
        z += fmaxf(s, 0.f) * sw2[i];
    }
    out[b] = __fdividef(1.f, 1.f + __expf(-z));
}

// ---------------- launch ----------------
extern "C" void kernel_launch(void* const* d_in, const int* in_sizes, int n_in,
                              void* d_out, int out_size) {
    const float* X    = (const float*)d_in[0];
    const float* W1ih = (const float*)d_in[1];
    const float* W1hh = (const float*)d_in[2];
    const float* b1ih = (const float*)d_in[3];
    const float* b1hh = (const float*)d_in[4];
    const float* W2ih = (const float*)d_in[5];
    const float* W2hh = (const float*)d_in[6];
    const float* b2ih = (const float*)d_in[7];
    const float* b2hh = (const float*)d_in[8];
    const float* fc1w = (const float*)d_in[9];
    const float* fc1b = (const float*)d_in[10];
    const float* fc2w = (const float*)d_in[11];
    const float* fc2b = (const float*)d_in[12];
    float* out = (float*)d_out;

    const int smem1 = SMEM1_FLOATS * (int)sizeof(float);  // 228480
    const int smem2 = SMEM2_FLOATS * (int)sizeof(float);  // 210944
    cudaFuncSetAttribute(lstm1_kernel, cudaFuncAttributeMaxDynamicSharedMemorySize, smem1);
    cudaFuncSetAttribute(lstm2_kernel, cudaFuncAttributeMaxDynamicSharedMemorySize, smem2);

    prep_kernel<<<456, 256>>>(W1ih, W1hh, b1ih, b1hh, W2ih, W2hh, b2ih, b2hh);
    lstm1_kernel<<<NBLK, 512, smem1>>>(X);
    lstm2_kernel<<<NBLK, 256, smem2>>>();
    head_kernel<<<4, 256>>>(fc1w, fc1b, fc2w, fc2b, out);
}